// round 3
// baseline (speedup 1.0000x reference)
#include <cuda_runtime.h>
#include <math.h>

// ---------------------------------------------------------------------------
// ReversedAttention, restructured:
//   S_b  = sum_{n unmasked} key_n (x) value_n          (big GEMM 1, fp32)
//   u_b  = masked key colsum ; w_b = value colsum ; c_b = count   (fused in GEMM1)
//   KtV  = Wk S Wv^T + (Wk u) bv^T + bk (Wv w + c bv)^T   (D x D, tiny)
//   aw   = softmax_d( KtV / sqrt(8) )
//   M_b  = Wq^T aw ;  r_b = bq^T aw
//   out  = query @ M_b + r_b                           (big GEMM 2, fp32)
// ---------------------------------------------------------------------------

#define NB 8
#define NN 8192
#define DD 256
#define NSPLIT 16     // stage-1 split over N
#define KT 16         // k-tile depth
#define STG 4         // cp.async pipeline stages

// ------------------------- device scratch (static, no allocs) --------------
__device__ float d_Spart[NSPLIT * NB * DD * DD];   // 32 MB
__device__ float d_S[NB * DD * DD];
__device__ float d_T1[NB * DD * DD];
__device__ float d_P[NB * DD * DD];
__device__ float d_M[NB * DD * DD];
__device__ float d_Upart[NSPLIT * NB * DD];
__device__ float d_Wpart[NSPLIT * NB * DD];
__device__ float d_Cpart[NSPLIT * NB];
__device__ float d_u[NB * DD];
__device__ float d_w[NB * DD];
__device__ float d_cc[NB];
__device__ float d_kv1[NB * DD];
__device__ float d_kv2[NB * DD];
__device__ float d_r[NB * DD];
__device__ int   g_mask_mode;   // 0 = 4-byte elements, 1 = 1-byte elements

// ------------------------- mask handling -----------------------------------
__global__ void detect_mask_kernel(const unsigned int* __restrict__ mw) {
    __shared__ int hasByte;
    if (threadIdx.x == 0) hasByte = 0;
    __syncthreads();
    int local = 0;
    for (int i = threadIdx.x; i < 16384; i += blockDim.x) {
        unsigned v = mw[i];
        if (v > 1u && v != 0x3F800000u) local = 1;
    }
    if (local) atomicOr(&hasByte, 1);
    __syncthreads();
    if (threadIdx.x == 0) g_mask_mode = hasByte ? 1 : 0;
}

__device__ __forceinline__ int mask_raw(const void* m, long i, int mode) {
    return (mode == 0) ? (((const unsigned int*)m)[i] != 0u)
                       : (((const unsigned char*)m)[i] != 0);
}

// ------------------------- cp.async helpers --------------------------------
__device__ __forceinline__ void cpa16(void* smem, const void* gmem) {
    unsigned sa = (unsigned)__cvta_generic_to_shared(smem);
    asm volatile("cp.async.cg.shared.global [%0], [%1], 16;"
                 :: "r"(sa), "l"(gmem));
}
__device__ __forceinline__ void cpa16z(void* smem, const void* gmem, int srcsz) {
    unsigned sa = (unsigned)__cvta_generic_to_shared(smem);
    asm volatile("cp.async.cg.shared.global [%0], [%1], 16, %2;"
                 :: "r"(sa), "l"(gmem), "r"(srcsz));
}
__device__ __forceinline__ void cpa_commit() {
    asm volatile("cp.async.commit_group;" ::: "memory");
}
__device__ __forceinline__ void cpa_wait2() {
    asm volatile("cp.async.wait_group 2;" ::: "memory");
}

// ------------------------- stage 1: S = key_masked^T @ value ---------------
// 128x128 tile, 256 threads, 8x8/thread, FFMA2, 4-stage cp.async pipeline.
// Mask applied via cp.async zero-fill (src-size 0 for padded rows).
// Diagonal blocks additionally produce masked key colsums (u) and value
// colsums (w); block (0,0) produces the unmasked count c.
__global__ __launch_bounds__(256, 2) void stage1_kernel(
    const float* __restrict__ key, const float* __restrict__ value,
    const void* __restrict__ mask)
{
    __shared__ float As[STG][KT][132];
    __shared__ float Bs[STG][KT][132];
    __shared__ float cntsh[KT];

    int t  = threadIdx.x;
    int b  = blockIdx.z >> 4;
    int sp = blockIdx.z & 15;
    int d0 = blockIdx.x * 128, e0 = blockIdx.y * 128;
    int diag  = (blockIdx.x == blockIdx.y);
    int zero0 = (d0 == 0 && e0 == 0);
    int mode = g_mask_mode;

    const int chunk = NN / NSPLIT;   // 512
    long nbase = (long)b * NN + (long)sp * chunk;
    const float* kb = key   + nbase * DD;
    const float* vb = value + nbase * DD;

    int td = t & 15, te = t >> 4;
    // copy mapping: chunks t and t+256 of 512 float4-chunks per array
    int r0 = t >> 5,         q0 = (t & 31) << 2;
    int r1 = (t + 256) >> 5, q1 = q0;

    auto issue = [&](int kt0, int s) {
        long n0r = nbase + kt0 + r0;
        long n1r = nbase + kt0 + r1;
        int sz0 = mask_raw(mask, n0r, mode) ? 0 : 16;
        int sz1 = mask_raw(mask, n1r, mode) ? 0 : 16;
        cpa16z(&As[s][r0][q0], kb + (long)(kt0 + r0) * DD + d0 + q0, sz0);
        cpa16z(&As[s][r1][q1], kb + (long)(kt0 + r1) * DD + d0 + q1, sz1);
        cpa16 (&Bs[s][r0][q0], vb + (long)(kt0 + r0) * DD + e0 + q0);
        cpa16 (&Bs[s][r1][q1], vb + (long)(kt0 + r1) * DD + e0 + q1);
        cpa_commit();
    };

    unsigned long long acc[32];
    #pragma unroll
    for (int i = 0; i < 32; i++) acc[i] = 0ull;
    float colsum = 0.f, cnt = 0.f;

    const int ntiles = chunk / KT;   // 32
    issue(0, 0); issue(KT, 1); issue(2 * KT, 2);

    for (int i = 0; i < ntiles; i++) {
        cpa_wait2();
        __syncthreads();
        if (i + 3 < ntiles) issue((i + 3) * KT, (i + 3) & 3);
        int s = i & 3;

        #pragma unroll
        for (int k = 0; k < KT; k++) {
            union { float4 f; unsigned long long u[2]; } b0, b1;
            b0.f = *(const float4*)&Bs[s][k][te * 8];
            b1.f = *(const float4*)&Bs[s][k][te * 8 + 4];
            float4 a0 = *(const float4*)&As[s][k][td * 8];
            float4 a1 = *(const float4*)&As[s][k][td * 8 + 4];
            float av[8] = {a0.x, a0.y, a0.z, a0.w, a1.x, a1.y, a1.z, a1.w};
            unsigned long long bp[4] = {b0.u[0], b0.u[1], b1.u[0], b1.u[1]};
            #pragma unroll
            for (int r = 0; r < 8; r++) {
                unsigned long long ad;
                unsigned ai = __float_as_uint(av[r]);
                asm("mov.b64 %0, {%1, %1};" : "=l"(ad) : "r"(ai));
                #pragma unroll
                for (int c = 0; c < 4; c++)
                    asm("fma.rn.f32x2 %0, %1, %2, %0;"
                        : "+l"(acc[r * 4 + c]) : "l"(ad), "l"(bp[c]));
            }
        }

        if (diag) {   // masked key colsum (As) / value colsum (Bs)
            int cc = t & 127;
            const float* col = (t < 128) ? &As[s][0][cc] : &Bs[s][0][cc];
            float sacc = 0.f;
            #pragma unroll
            for (int k = 0; k < KT; k++) sacc += col[k * 132];
            colsum += sacc;
        }
        if (zero0 && t < KT)
            cnt += mask_raw(mask, nbase + (long)i * KT + t, mode) ? 0.f : 1.f;
    }

    float* outp = d_Spart + ((long)(sp * NB + b) << 16);
    #pragma unroll
    for (int r = 0; r < 8; r++) {
        int d = d0 + td * 8 + r;
        #pragma unroll
        for (int c = 0; c < 4; c++)
            *(unsigned long long*)&outp[(long)d * DD + e0 + te * 8 + c * 2] =
                acc[r * 4 + c];
    }
    if (diag) {
        int cc = t & 127;
        if (t < 128) d_Upart[(sp * NB + b) * DD + d0 + cc] = colsum;
        else         d_Wpart[(sp * NB + b) * DD + e0 + cc] = colsum;
    }
    if (zero0) {
        if (t < KT) cntsh[t] = cnt;
        __syncthreads();
        if (t == 0) {
            float s = 0.f;
            #pragma unroll
            for (int k = 0; k < KT; k++) s += cntsh[k];
            d_Cpart[sp * NB + b] = s;
        }
    }
}

__global__ void s_reduce_kernel() {
    long i = (long)blockIdx.x * 256 + threadIdx.x;
    int b = (int)(i >> 16);
    int j = (int)(i & 65535);
    float s = 0.f;
    #pragma unroll
    for (int sp = 0; sp < NSPLIT; sp++)
        s += d_Spart[((long)(sp * NB + b) << 16) + j];
    d_S[((long)b << 16) + j] = s;
}

__global__ void uvw_reduce_kernel() {
    int b = blockIdx.x, d = threadIdx.x;
    float su = 0.f, sw = 0.f;
    #pragma unroll
    for (int sp = 0; sp < NSPLIT; sp++) {
        su += d_Upart[(sp * NB + b) * DD + d];
        sw += d_Wpart[(sp * NB + b) * DD + d];
    }
    d_u[b * DD + d] = su;
    d_w[b * DD + d] = sw;
    if (d == 0) {
        float c = 0.f;
        #pragma unroll
        for (int sp = 0; sp < NSPLIT; sp++) c += d_Cpart[sp * NB + b];
        d_cc[b] = c;
    }
}

// ------------------------- kv vectors: kv1 = Wk u, kv2 = Wv w + c bv -------
__global__ void kv_kernel(const float* __restrict__ Wk,
                          const float* __restrict__ Wv,
                          const float* __restrict__ bv) {
    int b = blockIdx.x, d = threadIdx.x;
    __shared__ float su[DD], sw[DD];
    su[d] = d_u[b * DD + d];
    sw[d] = d_w[b * DD + d];
    __syncthreads();
    float s1 = 0.f, s2 = 0.f;
    for (int i = 0; i < DD; i++) {
        s1 = fmaf(Wk[(long)d * DD + i], su[i], s1);
        s2 = fmaf(Wv[(long)d * DD + i], sw[i], s2);
    }
    d_kv1[b * DD + d] = s1;
    d_kv2[b * DD + d] = s2 + d_cc[b] * bv[d];
}

// ------------------------- small batched 256x256x256 GEMM ------------------
template<bool TA, bool TB, bool EPI>
__global__ __launch_bounds__(128) void sgemm_k(
    const float* __restrict__ A, long sA,
    const float* __restrict__ B, long sB,
    float* __restrict__ C,
    const float* __restrict__ x1, int sx1,
    const float* __restrict__ y1, int sy1,
    const float* __restrict__ x2, int sx2,
    const float* __restrict__ y2, int sy2,
    float scale)
{
    __shared__ float As[16][36];
    __shared__ float Bs[16][68];
    int t = threadIdx.x;
    int b = blockIdx.z;
    int d0 = blockIdx.x * 32, e0 = blockIdx.y * 64;
    const float* Ab = A + (long)b * sA;
    const float* Bb = B + (long)b * sB;
    int td = t & 7, te = t >> 3;

    float acc[4][4];
    #pragma unroll
    for (int r = 0; r < 4; r++)
        #pragma unroll
        for (int c = 0; c < 4; c++) acc[r][c] = 0.f;

    for (int kt = 0; kt < DD; kt += 16) {
        if (TA) {
            int row = t >> 3, col = (t & 7) * 4;
            *(float4*)&As[row][col] =
                *(const float4*)&Ab[(long)(kt + row) * DD + d0 + col];
        } else {
            int row = t >> 2, col = (t & 3) * 4;
            float4 v = *(const float4*)&Ab[(long)(d0 + row) * DD + kt + col];
            As[col + 0][row] = v.x; As[col + 1][row] = v.y;
            As[col + 2][row] = v.z; As[col + 3][row] = v.w;
        }
        #pragma unroll
        for (int h = 0; h < 2; h++) {
            int idx = t * 4 + h * 512;
            if (TB) {
                int row = idx >> 4, col = idx & 15;
                float4 v = *(const float4*)&Bb[(long)(e0 + row) * DD + kt + col];
                Bs[col + 0][row] = v.x; Bs[col + 1][row] = v.y;
                Bs[col + 2][row] = v.z; Bs[col + 3][row] = v.w;
            } else {
                int row = idx >> 6, col = idx & 63;
                *(float4*)&Bs[row][col] =
                    *(const float4*)&Bb[(long)(kt + row) * DD + e0 + col];
            }
        }
        __syncthreads();
        #pragma unroll
        for (int k = 0; k < 16; k++) {
            float4 a  = *(const float4*)&As[k][td * 4];
            float4 bb = *(const float4*)&Bs[k][te * 4];
            float av[4] = {a.x, a.y, a.z, a.w};
            float bv2[4] = {bb.x, bb.y, bb.z, bb.w};
            #pragma unroll
            for (int r = 0; r < 4; r++)
                #pragma unroll
                for (int c = 0; c < 4; c++)
                    acc[r][c] = fmaf(av[r], bv2[c], acc[r][c]);
        }
        __syncthreads();
    }

    float* Cb = C + ((long)b << 16);
    #pragma unroll
    for (int r = 0; r < 4; r++) {
        int d = d0 + td * 4 + r;
        #pragma unroll
        for (int c = 0; c < 4; c++) {
            int e = e0 + te * 4 + c;
            float v = acc[r][c];
            if (EPI)
                v = (v + x1[b * sx1 + d] * y1[b * sy1 + e]
                       + x2[b * sx2 + d] * y2[b * sy2 + e]) * scale;
            Cb[(long)d * DD + e] = v;
        }
    }
}

// ------------------------- softmax over d (in-place on d_P) ----------------
__global__ void softmax_kernel() {
    int b = blockIdx.x, ec = blockIdx.y;
    int tx = threadIdx.x, ty = threadIdx.y;      // (64, 4)
    float* Pb = d_P + ((long)b << 16);
    int e = ec * 64 + tx;
    __shared__ float red[4][64];

    float mx = -3.4e38f;
    for (int d = ty; d < DD; d += 4) mx = fmaxf(mx, Pb[(long)d * DD + e]);
    red[ty][tx] = mx;
    __syncthreads();
    mx = fmaxf(fmaxf(red[0][tx], red[1][tx]), fmaxf(red[2][tx], red[3][tx]));
    __syncthreads();

    float s = 0.f;
    for (int d = ty; d < DD; d += 4) {
        float ev = expf(Pb[(long)d * DD + e] - mx);
        Pb[(long)d * DD + e] = ev;
        s += ev;
    }
    red[ty][tx] = s;
    __syncthreads();
    float tot = red[0][tx] + red[1][tx] + red[2][tx] + red[3][tx];
    float inv = 1.0f / tot;
    for (int d = ty; d < DD; d += 4) Pb[(long)d * DD + e] *= inv;
}

// ------------------------- r = bq^T aw -------------------------------------
__global__ void rvec_kernel(const float* __restrict__ bq) {
    int b = blockIdx.x, e = threadIdx.x;
    const float* Pb = d_P + ((long)b << 16);
    float s = 0.f;
    for (int d = 0; d < DD; d++) s = fmaf(bq[d], Pb[(long)d * DD + e], s);
    d_r[b * DD + e] = s;
}

// ------------------------- stage 3: out = query @ M + r --------------------
// Register-double-buffered: prefetch tile i+1 from GMEM while computing i.
__global__ __launch_bounds__(256, 2) void stage3_kernel(
    const float* __restrict__ query, float* __restrict__ out)
{
    __shared__ float As[KT][132];   // [k][n]  (query, transposed)
    __shared__ float Bs[KT][132];   // [k][e]  (M)

    int t = threadIdx.x;
    int b = blockIdx.z;
    int n0 = blockIdx.x * 128, e0 = blockIdx.y * 128;

    const float* qb = query + (long)b * NN * DD;
    const float* Mb = d_M + ((long)b << 16);
    const float* rb = d_r + b * DD;

    int tn = t & 15, te = t >> 4;
    int ar = t & 127, acb = (t >> 7) * 8;       // A prefetch mapping
    int br0 = t >> 5,        bq0 = (t & 31) << 2;
    int br1 = (t >> 5) + 8;

    unsigned long long acc[32];
    #pragma unroll
    for (int i = 0; i < 32; i++) acc[i] = 0ull;

    float4 pa0 = *(const float4*)&qb[(long)(n0 + ar) * DD + acb];
    float4 pa1 = *(const float4*)&qb[(long)(n0 + ar) * DD + acb + 4];
    float4 pb0 = *(const float4*)&Mb[(long)br0 * DD + e0 + bq0];
    float4 pb1 = *(const float4*)&Mb[(long)br1 * DD + e0 + bq0];

    const int ntiles = DD / KT;   // 16
    for (int i = 0; i < ntiles; i++) {
        __syncthreads();   // previous compute done before overwriting smem
        As[acb + 0][ar] = pa0.x; As[acb + 1][ar] = pa0.y;
        As[acb + 2][ar] = pa0.z; As[acb + 3][ar] = pa0.w;
        As[acb + 4][ar] = pa1.x; As[acb + 5][ar] = pa1.y;
        As[acb + 6][ar] = pa1.z; As[acb + 7][ar] = pa1.w;
        *(float4*)&Bs[br0][bq0] = pb0;
        *(float4*)&Bs[br1][bq0] = pb1;
        __syncthreads();
        if (i + 1 < ntiles) {
            int kt = (i + 1) * KT;
            pa0 = *(const float4*)&qb[(long)(n0 + ar) * DD + kt + acb];
            pa1 = *(const float4*)&qb[(long)(n0 + ar) * DD + kt + acb + 4];
            pb0 = *(const float4*)&Mb[(long)(kt + br0) * DD + e0 + bq0];
            pb1 = *(const float4*)&Mb[(long)(kt + br1) * DD + e0 + bq0];
        }
        #pragma unroll
        for (int k = 0; k < KT; k++) {
            union { float4 f; unsigned long long u[2]; } b0, b1;
            b0.f = *(const float4*)&Bs[k][te * 8];
            b1.f = *(const float4*)&Bs[k][te * 8 + 4];
            float4 a0 = *(const float4*)&As[k][tn * 8];
            float4 a1 = *(const float4*)&As[k][tn * 8 + 4];
            float av[8] = {a0.x, a0.y, a0.z, a0.w, a1.x, a1.y, a1.z, a1.w};
            unsigned long long bp[4] = {b0.u[0], b0.u[1], b1.u[0], b1.u[1]};
            #pragma unroll
            for (int r = 0; r < 8; r++) {
                unsigned long long ad;
                unsigned ai = __float_as_uint(av[r]);
                asm("mov.b64 %0, {%1, %1};" : "=l"(ad) : "r"(ai));
                #pragma unroll
                for (int c = 0; c < 4; c++)
                    asm("fma.rn.f32x2 %0, %1, %2, %0;"
                        : "+l"(acc[r * 4 + c]) : "l"(ad), "l"(bp[c]));
            }
        }
    }

    #pragma unroll
    for (int r = 0; r < 8; r++) {
        int n = n0 + tn * 8 + r;
        #pragma unroll
        for (int c = 0; c < 4; c++) {
            int e = e0 + te * 8 + c * 2;
            union { unsigned long long u; float2 f; } cv;
            cv.u = acc[r * 4 + c];
            float2 rv = *(const float2*)&rb[e];
            cv.f.x += rv.x; cv.f.y += rv.y;
            *(float2*)&out[((long)b * NN + n) * DD + e] = cv.f;
        }
    }
}

// ---------------------------------------------------------------------------
extern "C" void kernel_launch(void* const* d_in, const int* in_sizes, int n_in,
                              void* d_out, int out_size)
{
    const float* query = (const float*)d_in[0];
    const float* key   = (const float*)d_in[1];
    const float* value = (const float*)d_in[2];
    const void*  mask  = d_in[3];
    int wo = (n_in >= 11 && in_sizes[4] == 1) ? 5 : 4;
    const float* Wq = (const float*)d_in[wo + 0];
    const float* bq = (const float*)d_in[wo + 1];
    const float* Wk = (const float*)d_in[wo + 2];
    const float* bk = (const float*)d_in[wo + 3];
    const float* Wv = (const float*)d_in[wo + 4];
    const float* bv = (const float*)d_in[wo + 5];
    float* out = (float*)d_out;

    float *pS, *pT1, *pP, *pM, *pkv1, *pkv2;
    cudaGetSymbolAddress((void**)&pS,   d_S);
    cudaGetSymbolAddress((void**)&pT1,  d_T1);
    cudaGetSymbolAddress((void**)&pP,   d_P);
    cudaGetSymbolAddress((void**)&pM,   d_M);
    cudaGetSymbolAddress((void**)&pkv1, d_kv1);
    cudaGetSymbolAddress((void**)&pkv2, d_kv2);

    const float inv_sqrt8 = 0.35355339059327373f;

    detect_mask_kernel<<<1, 256>>>((const unsigned int*)mask);
    stage1_kernel<<<dim3(2, 2, NB * NSPLIT), 256>>>(key, value, mask);
    s_reduce_kernel<<<NB * DD * DD / 256, 256>>>();
    uvw_reduce_kernel<<<NB, DD>>>();
    kv_kernel<<<NB, DD>>>(Wk, Wv, bv);
    // T1 = Wk @ S
    sgemm_k<false, false, false><<<dim3(8, 4, NB), 128>>>(
        Wk, 0, pS, (long)DD * DD, pT1,
        nullptr, 0, nullptr, 0, nullptr, 0, nullptr, 0, 1.0f);
    // P = (T1 @ Wv^T + kv1*bv^T + bk*kv2^T) / sqrt(8)
    sgemm_k<false, true, true><<<dim3(8, 4, NB), 128>>>(
        pT1, (long)DD * DD, Wv, 0, pP,
        pkv1, DD, bv, 0, bk, 0, pkv2, DD, inv_sqrt8);
    softmax_kernel<<<dim3(NB, 4), dim3(64, 4)>>>();
    rvec_kernel<<<NB, DD>>>(bq);
    // M = Wq^T @ aw
    sgemm_k<true, false, false><<<dim3(8, 4, NB), 128>>>(
        Wq, 0, pP, (long)DD * DD, pM,
        nullptr, 0, nullptr, 0, nullptr, 0, nullptr, 0, 1.0f);
    stage3_kernel<<<dim3(64, 2, NB), 256>>>(query, out);
}

// round 5
// speedup vs baseline: 1.0166x; 1.0166x over previous
#include <cuda_runtime.h>
#include <math.h>
#include <stdint.h>

#define NB 8
#define NN 8192
#define DD 256
#define NSPLIT 16
#define KT 16
#define STG 4

__device__ float d_Spart[NSPLIT * NB * DD * DD];
__device__ float d_S[NB * DD * DD];
__device__ float d_T1[NB * DD * DD];
__device__ float d_P[NB * DD * DD];
__device__ float d_Mt_hi[NB * DD * DD];
__device__ float d_Mt_lo[NB * DD * DD];
__device__ float d_Upart[NSPLIT * NB * DD];
__device__ float d_Wpart[NSPLIT * NB * DD];
__device__ float d_Cpart[NSPLIT * NB];
__device__ float d_u[NB * DD];
__device__ float d_w[NB * DD];
__device__ float d_cc[NB];
__device__ float d_kv1[NB * DD];
__device__ float d_kv2[NB * DD];
__device__ float d_r[NB * DD];
__device__ int   g_mask_mode;

__device__ __forceinline__ float hi10(float x) {
    return __uint_as_float(__float_as_uint(x) & 0xFFFFE000u);
}

// ---------------- mask ----------------
__global__ void detect_mask_kernel(const unsigned int* __restrict__ mw) {
    __shared__ int hasByte;
    if (threadIdx.x == 0) hasByte = 0;
    __syncthreads();
    int local = 0;
    for (int i = threadIdx.x; i < 16384; i += blockDim.x) {
        unsigned v = mw[i];
        if (v > 1u && v != 0x3F800000u) local = 1;
    }
    if (local) atomicOr(&hasByte, 1);
    __syncthreads();
    if (threadIdx.x == 0) g_mask_mode = hasByte ? 1 : 0;
}
__device__ __forceinline__ int mask_raw(const void* m, long i, int mode) {
    return (mode == 0) ? (((const unsigned int*)m)[i] != 0u)
                       : (((const unsigned char*)m)[i] != 0);
}

// ---------------- cp.async ----------------
__device__ __forceinline__ void cpa16(void* s, const void* g) {
    unsigned sa = (unsigned)__cvta_generic_to_shared(s);
    asm volatile("cp.async.cg.shared.global [%0], [%1], 16;" :: "r"(sa), "l"(g));
}
__device__ __forceinline__ void cpa16z(void* s, const void* g, int sz) {
    unsigned sa = (unsigned)__cvta_generic_to_shared(s);
    asm volatile("cp.async.cg.shared.global [%0], [%1], 16, %2;" :: "r"(sa), "l"(g), "r"(sz));
}
#define CPA_COMMIT() asm volatile("cp.async.commit_group;" ::: "memory")
#define CPA_WAIT(n)  asm volatile("cp.async.wait_group %0;" :: "n"(n) : "memory")

// ---------------- tf32 mma.sync ----------------
__device__ __forceinline__ void mma168(float* c, const uint32_t* a, const uint32_t* b) {
    asm volatile("mma.sync.aligned.m16n8k8.row.col.f32.tf32.tf32.f32 "
        "{%0,%1,%2,%3}, {%4,%5,%6,%7}, {%8,%9}, {%0,%1,%2,%3};"
        : "+f"(c[0]), "+f"(c[1]), "+f"(c[2]), "+f"(c[3])
        : "r"(a[0]), "r"(a[1]), "r"(a[2]), "r"(a[3]), "r"(b[0]), "r"(b[1]));
}

// ---------------- stage 1: S = key_masked^T @ value (FFMA2) ----------------
__global__ __launch_bounds__(256, 2) void stage1_kernel(
    const float* __restrict__ key, const float* __restrict__ value,
    const void* __restrict__ mask)
{
    __shared__ float As[STG][KT][132];
    __shared__ float Bs[STG][KT][132];
    __shared__ float cntsh[KT];

    int t = threadIdx.x;
    int b = blockIdx.z >> 4, sp = blockIdx.z & 15;
    int d0 = blockIdx.x * 128, e0 = blockIdx.y * 128;
    int diag = (blockIdx.x == blockIdx.y);
    int zero0 = (d0 == 0 && e0 == 0);
    int mode = g_mask_mode;

    const int chunk = NN / NSPLIT;   // 512
    long nbase = (long)b * NN + (long)sp * chunk;
    const float* kb = key + nbase * DD;
    const float* vb = value + nbase * DD;

    int td = t & 15, te = t >> 4;
    int r0 = t >> 5, q0 = (t & 31) << 2;
    int r1 = r0 + 8;

    auto issue = [&](int kt0, int s) {
        int sz0 = mask_raw(mask, nbase + kt0 + r0, mode) ? 0 : 16;
        int sz1 = mask_raw(mask, nbase + kt0 + r1, mode) ? 0 : 16;
        cpa16z(&As[s][r0][q0], kb + (long)(kt0 + r0) * DD + d0 + q0, sz0);
        cpa16z(&As[s][r1][q0], kb + (long)(kt0 + r1) * DD + d0 + q0, sz1);
        cpa16 (&Bs[s][r0][q0], vb + (long)(kt0 + r0) * DD + e0 + q0);
        cpa16 (&Bs[s][r1][q0], vb + (long)(kt0 + r1) * DD + e0 + q0);
        CPA_COMMIT();
    };

    unsigned long long acc[32];
    #pragma unroll
    for (int i = 0; i < 32; i++) acc[i] = 0ull;
    float colsum = 0.f, cnt = 0.f;

    const int ntiles = chunk / KT;   // 32
    issue(0, 0); issue(KT, 1); issue(2 * KT, 2);

    for (int i = 0; i < ntiles; i++) {
        CPA_WAIT(2);
        __syncthreads();
        if (i + 3 < ntiles) issue((i + 3) * KT, (i + 3) & 3);
        int s = i & 3;
        #pragma unroll
        for (int k = 0; k < KT; k++) {
            union { float4 f; unsigned long long u[2]; } b0, b1;
            b0.f = *(const float4*)&Bs[s][k][te * 8];
            b1.f = *(const float4*)&Bs[s][k][te * 8 + 4];
            float4 a0 = *(const float4*)&As[s][k][td * 8];
            float4 a1 = *(const float4*)&As[s][k][td * 8 + 4];
            float av[8] = {a0.x, a0.y, a0.z, a0.w, a1.x, a1.y, a1.z, a1.w};
            unsigned long long bp[4] = {b0.u[0], b0.u[1], b1.u[0], b1.u[1]};
            #pragma unroll
            for (int r = 0; r < 8; r++) {
                unsigned long long ad;
                unsigned ai = __float_as_uint(av[r]);
                asm("mov.b64 %0, {%1, %1};" : "=l"(ad) : "r"(ai));
                #pragma unroll
                for (int c = 0; c < 4; c++)
                    asm("fma.rn.f32x2 %0, %1, %2, %0;"
                        : "+l"(acc[r * 4 + c]) : "l"(ad), "l"(bp[c]));
            }
        }
        if (diag) {
            int cc = t & 127;
            const float* col = (t < 128) ? &As[s][0][cc] : &Bs[s][0][cc];
            float sacc = 0.f;
            #pragma unroll
            for (int k = 0; k < KT; k++) sacc += col[k * 132];
            colsum += sacc;
        }
        if (zero0 && t < KT)
            cnt += mask_raw(mask, nbase + (long)i * KT + t, mode) ? 0.f : 1.f;
    }

    float* outp = d_Spart + ((long)(sp * NB + b) << 16);
    #pragma unroll
    for (int r = 0; r < 8; r++) {
        int d = d0 + td * 8 + r;
        #pragma unroll
        for (int c = 0; c < 4; c++)
            *(unsigned long long*)&outp[(long)d * DD + e0 + te * 8 + c * 2] = acc[r * 4 + c];
    }
    if (diag) {
        int cc = t & 127;
        if (t < 128) d_Upart[(sp * NB + b) * DD + d0 + cc] = colsum;
        else         d_Wpart[(sp * NB + b) * DD + e0 + cc] = colsum;
    }
    if (zero0) {
        if (t < KT) cntsh[t] = cnt;
        __syncthreads();
        if (t == 0) {
            float s = 0.f;
            #pragma unroll
            for (int k = 0; k < KT; k++) s += cntsh[k];
            d_Cpart[sp * NB + b] = s;
        }
    }
}

__global__ void s_reduce_kernel() {
    long i = (long)blockIdx.x * 256 + threadIdx.x;
    int b = (int)(i >> 16);
    int j = (int)(i & 65535);
    float s = 0.f;
    #pragma unroll
    for (int sp = 0; sp < NSPLIT; sp++)
        s += d_Spart[((long)(sp * NB + b) << 16) + j];
    d_S[((long)b << 16) + j] = s;
}

__global__ void uvw_reduce_kernel() {
    int b = blockIdx.x, d = threadIdx.x;
    float su = 0.f, sw = 0.f;
    #pragma unroll
    for (int sp = 0; sp < NSPLIT; sp++) {
        su += d_Upart[(sp * NB + b) * DD + d];
        sw += d_Wpart[(sp * NB + b) * DD + d];
    }
    d_u[b * DD + d] = su;
    d_w[b * DD + d] = sw;
    if (d == 0) {
        float c = 0.f;
        #pragma unroll
        for (int sp = 0; sp < NSPLIT; sp++) c += d_Cpart[sp * NB + b];
        d_cc[b] = c;
    }
}

__global__ void kv_kernel(const float* __restrict__ Wk,
                          const float* __restrict__ Wv,
                          const float* __restrict__ bv) {
    int b = blockIdx.x, d = threadIdx.x;
    __shared__ float su[DD], sw[DD];
    su[d] = d_u[b * DD + d];
    sw[d] = d_w[b * DD + d];
    __syncthreads();
    float s1 = 0.f, s2 = 0.f;
    for (int i = 0; i < DD; i++) {
        s1 = fmaf(Wk[(long)d * DD + i], su[i], s1);
        s2 = fmaf(Wv[(long)d * DD + i], sw[i], s2);
    }
    d_kv1[b * DD + d] = s1;
    d_kv2[b * DD + d] = s2 + d_cc[b] * bv[d];
}

// ---------------- small batched GEMM ----------------
template<bool TA, bool TB, bool EPI, bool SPL>
__global__ __launch_bounds__(128) void sgemm_k(
    const float* __restrict__ A, long sA,
    const float* __restrict__ B, long sB,
    float* __restrict__ C, float* __restrict__ C2,
    const float* __restrict__ x1, int sx1,
    const float* __restrict__ y1, int sy1,
    const float* __restrict__ x2, int sx2,
    const float* __restrict__ y2, int sy2,
    float scale)
{
    __shared__ float As[16][36];
    __shared__ float Bs[16][68];
    int t = threadIdx.x;
    int b = blockIdx.z;
    int d0 = blockIdx.x * 32, e0 = blockIdx.y * 64;
    const float* Ab = A + (long)b * sA;
    const float* Bb = B + (long)b * sB;
    int td = t & 7, te = t >> 3;

    float acc[4][4];
    #pragma unroll
    for (int r = 0; r < 4; r++)
        #pragma unroll
        for (int c = 0; c < 4; c++) acc[r][c] = 0.f;

    for (int kt = 0; kt < DD; kt += 16) {
        if (TA) {
            int row = t >> 3, col = (t & 7) * 4;
            *(float4*)&As[row][col] = *(const float4*)&Ab[(long)(kt + row) * DD + d0 + col];
        } else {
            int row = t >> 2, col = (t & 3) * 4;
            float4 v = *(const float4*)&Ab[(long)(d0 + row) * DD + kt + col];
            As[col + 0][row] = v.x; As[col + 1][row] = v.y;
            As[col + 2][row] = v.z; As[col + 3][row] = v.w;
        }
        #pragma unroll
        for (int h = 0; h < 2; h++) {
            int idx = t * 4 + h * 512;
            if (TB) {
                int row = idx >> 4, col = idx & 15;
                float4 v = *(const float4*)&Bb[(long)(e0 + row) * DD + kt + col];
                Bs[col + 0][row] = v.x; Bs[col + 1][row] = v.y;
                Bs[col + 2][row] = v.z; Bs[col + 3][row] = v.w;
            } else {
                int row = idx >> 6, col = idx & 63;
                *(float4*)&Bs[row][col] = *(const float4*)&Bb[(long)(kt + row) * DD + e0 + col];
            }
        }
        __syncthreads();
        #pragma unroll
        for (int k = 0; k < 16; k++) {
            float4 a = *(const float4*)&As[k][td * 4];
            float4 bb = *(const float4*)&Bs[k][te * 4];
            float av[4] = {a.x, a.y, a.z, a.w};
            float bv2[4] = {bb.x, bb.y, bb.z, bb.w};
            #pragma unroll
            for (int r = 0; r < 4; r++)
                #pragma unroll
                for (int c = 0; c < 4; c++)
                    acc[r][c] = fmaf(av[r], bv2[c], acc[r][c]);
        }
        __syncthreads();
    }

    #pragma unroll
    for (int r = 0; r < 4; r++) {
        int d = d0 + td * 4 + r;
        #pragma unroll
        for (int c = 0; c < 4; c++) {
            int e = e0 + te * 4 + c;
            float v = acc[r][c];
            if (EPI)
                v = (v + x1[b * sx1 + d] * y1[b * sy1 + e]
                       + x2[b * sx2 + d] * y2[b * sy2 + e]) * scale;
            long off = ((long)b << 16) + (long)d * DD + e;
            if (SPL) {
                float h = hi10(v);
                C[off] = h;
                C2[off] = v - h;
            } else {
                C[off] = v;
            }
        }
    }
}

// ---------------- softmax over d (in-place d_P) ----------------
__global__ void softmax_kernel() {
    int b = blockIdx.x, ec = blockIdx.y;
    int tx = threadIdx.x, ty = threadIdx.y;
    float* Pb = d_P + ((long)b << 16);
    int e = ec * 64 + tx;
    __shared__ float red[4][64];

    float mx = -3.4e38f;
    for (int d = ty; d < DD; d += 4) mx = fmaxf(mx, Pb[(long)d * DD + e]);
    red[ty][tx] = mx;
    __syncthreads();
    mx = fmaxf(fmaxf(red[0][tx], red[1][tx]), fmaxf(red[2][tx], red[3][tx]));
    __syncthreads();
    float s = 0.f;
    for (int d = ty; d < DD; d += 4) {
        float ev = expf(Pb[(long)d * DD + e] - mx);
        Pb[(long)d * DD + e] = ev;
        s += ev;
    }
    red[ty][tx] = s;
    __syncthreads();
    float inv = 1.0f / (red[0][tx] + red[1][tx] + red[2][tx] + red[3][tx]);
    for (int d = ty; d < DD; d += 4) Pb[(long)d * DD + e] *= inv;
}

__global__ void rvec_kernel(const float* __restrict__ bq) {
    int b = blockIdx.x, e = threadIdx.x;
    const float* Pb = d_P + ((long)b << 16);
    float s = 0.f;
    for (int d = 0; d < DD; d++) s = fmaf(bq[d], Pb[(long)d * DD + e], s);
    d_r[b * DD + e] = s;
}

// ---------------- stage 3: out = q @ M + r  (mma.sync 3xTF32) --------------
// Block 128n x 128e, 8 warps (4n x 2e), warp 32n x 64e. K chunks of 32,
// double-buffered smem. A (query) split hi/lo on the fly; B = Mt pre-split.
#define S3_AH 0
#define S3_AL 4224          // 32*132
#define S3_BH 8448
#define S3_BL 13568         // 8448 + 128*40
#define S3_STRIDE 18688     // floats per stage
#define S3_SMEM (2 * S3_STRIDE * 4)

__global__ __launch_bounds__(256, 1) void stage3_mma_kernel(
    const float* __restrict__ query, float* __restrict__ out)
{
    extern __shared__ float sm[];
    __shared__ float rsh[DD];
    int t = threadIdx.x, lane = t & 31, wid = t >> 5;
    int b = blockIdx.z;
    long n0 = (long)blockIdx.x * 128;
    int e0 = blockIdx.y * 128;
    const float* qb = query + ((long)b * NN + n0) * DD;
    const float* Bhp = d_Mt_hi + ((long)b << 16) + (long)e0 * DD;
    const float* Blp = d_Mt_lo + ((long)b << 16) + (long)e0 * DD;
    if (t < DD) rsh[t] = d_r[b * DD + t];

    int wn = wid & 3, we = wid >> 2;
    int g = lane >> 2, tg = lane & 3;

    auto loadB = [&](int c, int s) {
        float* Bsm = sm + s * S3_STRIDE;
        #pragma unroll
        for (int i = 0; i < 4; i++) {
            int idx = t + i * 256;
            int row = idx >> 3, c4 = idx & 7;
            cpa16(Bsm + S3_BH + row * 40 + c4 * 4, Bhp + (long)row * DD + c * 32 + c4 * 4);
            cpa16(Bsm + S3_BL + row * 40 + c4 * 4, Blp + (long)row * DD + c * 32 + c4 * 4);
        }
        CPA_COMMIT();
    };
    auto loadA = [&](int c, int s) {
        float* Asm = sm + s * S3_STRIDE;
        #pragma unroll
        for (int i = 0; i < 4; i++) {
            int idx = t + i * 256;
            int row = idx >> 3, c4 = idx & 7;
            float4 v = *(const float4*)(qb + (long)row * DD + c * 32 + c4 * 4);
            float h;
            h = hi10(v.x); Asm[S3_AH + (c4 * 4 + 0) * 132 + row] = h;
                           Asm[S3_AL + (c4 * 4 + 0) * 132 + row] = v.x - h;
            h = hi10(v.y); Asm[S3_AH + (c4 * 4 + 1) * 132 + row] = h;
                           Asm[S3_AL + (c4 * 4 + 1) * 132 + row] = v.y - h;
            h = hi10(v.z); Asm[S3_AH + (c4 * 4 + 2) * 132 + row] = h;
                           Asm[S3_AL + (c4 * 4 + 2) * 132 + row] = v.z - h;
            h = hi10(v.w); Asm[S3_AH + (c4 * 4 + 3) * 132 + row] = h;
                           Asm[S3_AL + (c4 * 4 + 3) * 132 + row] = v.w - h;
        }
    };

    float acc[2][8][4];
    #pragma unroll
    for (int mi = 0; mi < 2; mi++)
        #pragma unroll
        for (int ni = 0; ni < 8; ni++)
            #pragma unroll
            for (int j = 0; j < 4; j++) acc[mi][ni][j] = 0.f;

    loadB(0, 0); loadA(0, 0);

    for (int c = 0; c < 8; c++) {
        int s = c & 1;
        CPA_WAIT(0);
        __syncthreads();
        if (c < 7) { loadB(c + 1, 1 - s); loadA(c + 1, 1 - s); }
        const float* Asm = sm + s * S3_STRIDE;
        const float* Bsm = sm + s * S3_STRIDE;
        #pragma unroll
        for (int j = 0; j < 4; j++) {
            int k8 = j * 8;
            uint32_t ah[2][4], al[2][4], bh[8][2], bl[8][2];
            #pragma unroll
            for (int mi = 0; mi < 2; mi++) {
                int nr = wn * 32 + mi * 16;
                ah[mi][0] = __float_as_uint(Asm[S3_AH + (k8 + tg) * 132 + nr + g]);
                ah[mi][1] = __float_as_uint(Asm[S3_AH + (k8 + tg) * 132 + nr + g + 8]);
                ah[mi][2] = __float_as_uint(Asm[S3_AH + (k8 + tg + 4) * 132 + nr + g]);
                ah[mi][3] = __float_as_uint(Asm[S3_AH + (k8 + tg + 4) * 132 + nr + g + 8]);
                al[mi][0] = __float_as_uint(Asm[S3_AL + (k8 + tg) * 132 + nr + g]);
                al[mi][1] = __float_as_uint(Asm[S3_AL + (k8 + tg) * 132 + nr + g + 8]);
                al[mi][2] = __float_as_uint(Asm[S3_AL + (k8 + tg + 4) * 132 + nr + g]);
                al[mi][3] = __float_as_uint(Asm[S3_AL + (k8 + tg + 4) * 132 + nr + g + 8]);
            }
            #pragma unroll
            for (int ni = 0; ni < 8; ni++) {
                int e = we * 64 + ni * 8 + g;
                bh[ni][0] = __float_as_uint(Bsm[S3_BH + e * 40 + k8 + tg]);
                bh[ni][1] = __float_as_uint(Bsm[S3_BH + e * 40 + k8 + tg + 4]);
                bl[ni][0] = __float_as_uint(Bsm[S3_BL + e * 40 + k8 + tg]);
                bl[ni][1] = __float_as_uint(Bsm[S3_BL + e * 40 + k8 + tg + 4]);
            }
            #pragma unroll
            for (int mi = 0; mi < 2; mi++)
                #pragma unroll
                for (int ni = 0; ni < 8; ni++) {
                    mma168(acc[mi][ni], ah[mi], bh[ni]);
                    mma168(acc[mi][ni], ah[mi], bl[ni]);
                    mma168(acc[mi][ni], al[mi], bh[ni]);
                }
        }
    }

    // epilogue: out[n][e] = acc + r[e]
    #pragma unroll
    for (int mi = 0; mi < 2; mi++) {
        long nr = n0 + wn * 32 + mi * 16;
        #pragma unroll
        for (int ni = 0; ni < 8; ni++) {
            int eg = e0 + we * 64 + ni * 8 + tg * 2;
            float2 v0, v1;
            v0.x = acc[mi][ni][0] + rsh[eg];
            v0.y = acc[mi][ni][1] + rsh[eg + 1];
            v1.x = acc[mi][ni][2] + rsh[eg];
            v1.y = acc[mi][ni][3] + rsh[eg + 1];
            *(float2*)(out + ((long)b * NN + nr + g) * DD + eg) = v0;
            *(float2*)(out + ((long)b * NN + nr + g + 8) * DD + eg) = v1;
        }
    }
}

// ---------------------------------------------------------------------------
extern "C" void kernel_launch(void* const* d_in, const int* in_sizes, int n_in,
                              void* d_out, int out_size)
{
    const float* query = (const float*)d_in[0];
    const float* key   = (const float*)d_in[1];
    const float* value = (const float*)d_in[2];
    const void*  mask  = d_in[3];
    int wo = (n_in >= 11 && in_sizes[4] == 1) ? 5 : 4;
    const float* Wq = (const float*)d_in[wo + 0];
    const float* bq = (const float*)d_in[wo + 1];
    const float* Wk = (const float*)d_in[wo + 2];
    const float* bk = (const float*)d_in[wo + 3];
    const float* Wv = (const float*)d_in[wo + 4];
    const float* bv = (const float*)d_in[wo + 5];
    float* out = (float*)d_out;

    float *pS, *pT1, *pP, *pMh, *pMl, *pkv1, *pkv2;
    cudaGetSymbolAddress((void**)&pS, d_S);
    cudaGetSymbolAddress((void**)&pT1, d_T1);
    cudaGetSymbolAddress((void**)&pP, d_P);
    cudaGetSymbolAddress((void**)&pMh, d_Mt_hi);
    cudaGetSymbolAddress((void**)&pMl, d_Mt_lo);
    cudaGetSymbolAddress((void**)&pkv1, d_kv1);
    cudaGetSymbolAddress((void**)&pkv2, d_kv2);

    cudaFuncSetAttribute(stage3_mma_kernel,
                         cudaFuncAttributeMaxDynamicSharedMemorySize, S3_SMEM);

    const float inv_sqrt8 = 0.35355339059327373f;

    detect_mask_kernel<<<1, 256>>>((const unsigned int*)mask);
    stage1_kernel<<<dim3(2, 2, NB * NSPLIT), 256>>>(key, value, mask);
    s_reduce_kernel<<<NB * DD * DD / 256, 256>>>();
    uvw_reduce_kernel<<<NB, DD>>>();
    kv_kernel<<<NB, DD>>>(Wk, Wv, bv);
    // T1 = Wk @ S
    sgemm_k<false, false, false, false><<<dim3(8, 4, NB), 128>>>(
        Wk, 0, pS, (long)DD * DD, pT1, nullptr,
        nullptr, 0, nullptr, 0, nullptr, 0, nullptr, 0, 1.0f);
    // P = (T1 @ Wv^T + kv1*bv^T + bk*kv2^T) / sqrt(8)
    sgemm_k<false, true, true, false><<<dim3(8, 4, NB), 128>>>(
        pT1, (long)DD * DD, Wv, 0, pP, nullptr,
        pkv1, DD, bv, 0, bk, 0, pkv2, DD, inv_sqrt8);
    softmax_kernel<<<dim3(NB, 4), dim3(64, 4)>>>();
    rvec_kernel<<<NB, DD>>>(bq);
    // Mt = aw^T @ Wq  -> Mt[e][d], hi/lo split epilogue
    sgemm_k<true, false, false, true><<<dim3(8, 4, NB), 128>>>(
        pP, (long)DD * DD, Wq, 0, pMh, pMl,
        nullptr, 0, nullptr, 0, nullptr, 0, nullptr, 0, 1.0f);
    stage3_mma_kernel<<<dim3(64, 2, NB), 256, S3_SMEM>>>(query, out);
}

// round 6
// speedup vs baseline: 1.2612x; 1.2406x over previous
#include <cuda_runtime.h>
#include <cuda_fp16.h>
#include <math.h>
#include <stdint.h>

#define NB 8
#define NN 8192
#define DD 256
#define NSPLIT 16
#define KT 16

__device__ float d_Spart[NSPLIT * NB * DD * DD];
__device__ float d_S[NB * DD * DD];
__device__ float d_T1[NB * DD * DD];
__device__ float d_P[NB * DD * DD];
__device__ __half d_Mth[NB * DD * DD];
__device__ __half d_Mtl[NB * DD * DD];
__device__ float d_Upart[NSPLIT * NB * DD];
__device__ float d_Wpart[NSPLIT * NB * DD];
__device__ float d_Cpart[NSPLIT * NB];
__device__ float d_u[NB * DD];
__device__ float d_w[NB * DD];
__device__ float d_cc[NB];
__device__ float d_kv1[NB * DD];
__device__ float d_kv2[NB * DD];
__device__ float d_r[NB * DD];
__device__ int   g_mask_mode;

// ---------------- helpers ----------------
__global__ void detect_mask_kernel(const unsigned int* __restrict__ mw) {
    __shared__ int hasByte;
    if (threadIdx.x == 0) hasByte = 0;
    __syncthreads();
    int local = 0;
    for (int i = threadIdx.x; i < 16384; i += blockDim.x) {
        unsigned v = mw[i];
        if (v > 1u && v != 0x3F800000u) local = 1;
    }
    if (local) atomicOr(&hasByte, 1);
    __syncthreads();
    if (threadIdx.x == 0) g_mask_mode = hasByte ? 1 : 0;
}
__device__ __forceinline__ int mask_raw(const void* m, long i, int mode) {
    return (mode == 0) ? (((const unsigned int*)m)[i] != 0u)
                       : (((const unsigned char*)m)[i] != 0);
}
__device__ __forceinline__ void cpa16(void* s, const void* g) {
    unsigned sa = (unsigned)__cvta_generic_to_shared(s);
    asm volatile("cp.async.cg.shared.global [%0], [%1], 16;" :: "r"(sa), "l"(g));
}
#define CPA_COMMIT() asm volatile("cp.async.commit_group;" ::: "memory")
#define CPA_WAIT(n)  asm volatile("cp.async.wait_group %0;" :: "n"(n) : "memory")

// fp16 mma m16n8k16, fp32 accum
__device__ __forceinline__ void mma16816(float* c, const uint32_t* a, const uint32_t* b) {
    asm volatile("mma.sync.aligned.m16n8k16.row.col.f32.f16.f16.f32 "
        "{%0,%1,%2,%3}, {%4,%5,%6,%7}, {%8,%9}, {%0,%1,%2,%3};"
        : "+f"(c[0]), "+f"(c[1]), "+f"(c[2]), "+f"(c[3])
        : "r"(a[0]), "r"(a[1]), "r"(a[2]), "r"(a[3]), "r"(b[0]), "r"(b[1]));
}
// pack (x0,x1) -> half2 hi + half2 lo residual
__device__ __forceinline__ void split2(float x0, float x1, uint32_t& h, uint32_t& l) {
    __half2 hh = __floats2half2_rn(x0, x1);
    __half2 ll = __floats2half2_rn(x0 - __low2float(hh), x1 - __high2float(hh));
    h = *(uint32_t*)&hh;
    l = *(uint32_t*)&ll;
}

// ---------------- stage 1: S = key_masked^T @ value (fp16x3 mma) ----------
// CTA: 128d x 128e, K = n chunk of 512 (NSPLIT). 8 warps (4d x 2e).
// smem layout per array: [row][k-pair] u32(half2), stride 9, xor swizzle.
__global__ __launch_bounds__(256, 2) void stage1_kernel(
    const float* __restrict__ key, const float* __restrict__ value,
    const void* __restrict__ mask)
{
    __shared__ uint32_t Ah[2][128 * 9], Al[2][128 * 9];
    __shared__ uint32_t Bh[2][128 * 9], Bl[2][128 * 9];
    __shared__ float cntsh[KT];

    int t = threadIdx.x, lane = t & 31, wid = t >> 5;
    int b = blockIdx.z >> 4, sp = blockIdx.z & 15;
    int d0 = blockIdx.x * 128, e0 = blockIdx.y * 128;
    int diag = (blockIdx.x == blockIdx.y);
    int zero0 = (d0 == 0 && e0 == 0);
    int mode = g_mask_mode;

    const int chunk = NN / NSPLIT;   // 512
    long nbase = (long)b * NN + (long)sp * chunk;
    const float* kb = key + nbase * DD;
    const float* vb = value + nbase * DD;

    int p = wid;                 // warp owns n-pair 2p, 2p+1
    int dq = lane * 4;
    int wn = wid & 3, we = wid >> 2, g = lane >> 2, tg = lane & 3;
    auto off = [](int r, int pp) { return r * 9 + (pp ^ (r & 7)); };

    float acc[2][8][4];
    #pragma unroll
    for (int mi = 0; mi < 2; mi++)
        #pragma unroll
        for (int ni = 0; ni < 8; ni++)
            #pragma unroll
            for (int j = 0; j < 4; j++) acc[mi][ni][j] = 0.f;
    float colsum = 0.f, cnt = 0.f;

    float4 k0, k1, v0, v1;
    float m0, m1;
    auto ldt = [&](int kt0) {
        long n0 = nbase + kt0 + 2 * p;
        m0 = mask_raw(mask, n0, mode) ? 0.f : 1.f;
        m1 = mask_raw(mask, n0 + 1, mode) ? 0.f : 1.f;
        k0 = *(const float4*)(kb + (long)(kt0 + 2 * p) * DD + d0 + dq);
        k1 = *(const float4*)(kb + (long)(kt0 + 2 * p + 1) * DD + d0 + dq);
        v0 = *(const float4*)(vb + (long)(kt0 + 2 * p) * DD + e0 + dq);
        v1 = *(const float4*)(vb + (long)(kt0 + 2 * p + 1) * DD + e0 + dq);
    };

    const int ntiles = chunk / KT;   // 32
    ldt(0);

    for (int i = 0; i < ntiles; i++) {
        int s = i & 1;
        {   // convert + transposed STS
            float ka[4] = {k0.x * m0, k0.y * m0, k0.z * m0, k0.w * m0};
            float kc[4] = {k1.x * m1, k1.y * m1, k1.z * m1, k1.w * m1};
            float va[4] = {v0.x, v0.y, v0.z, v0.w};
            float vc[4] = {v1.x, v1.y, v1.z, v1.w};
            #pragma unroll
            for (int j = 0; j < 4; j++) {
                int o = off(dq + j, p);
                uint32_t h, l;
                split2(ka[j], kc[j], h, l);
                Ah[s][o] = h; Al[s][o] = l;
                split2(va[j], vc[j], h, l);
                Bh[s][o] = h; Bl[s][o] = l;
            }
        }
        __syncthreads();
        if (i + 1 < ntiles) ldt((i + 1) * KT);

        uint32_t ah[2][4], al[2][4];
        #pragma unroll
        for (int mi = 0; mi < 2; mi++) {
            int r = wn * 32 + mi * 16 + g;
            ah[mi][0] = Ah[s][off(r, tg)];     ah[mi][1] = Ah[s][off(r + 8, tg)];
            ah[mi][2] = Ah[s][off(r, tg + 4)]; ah[mi][3] = Ah[s][off(r + 8, tg + 4)];
            al[mi][0] = Al[s][off(r, tg)];     al[mi][1] = Al[s][off(r + 8, tg)];
            al[mi][2] = Al[s][off(r, tg + 4)]; al[mi][3] = Al[s][off(r + 8, tg + 4)];
        }
        #pragma unroll
        for (int ni = 0; ni < 8; ni++) {
            int e = we * 64 + ni * 8 + g;
            uint32_t bhf[2] = {Bh[s][off(e, tg)], Bh[s][off(e, tg + 4)]};
            uint32_t blf[2] = {Bl[s][off(e, tg)], Bl[s][off(e, tg + 4)]};
            #pragma unroll
            for (int mi = 0; mi < 2; mi++) {
                mma16816(acc[mi][ni], ah[mi], bhf);
                mma16816(acc[mi][ni], ah[mi], blf);
                mma16816(acc[mi][ni], al[mi], bhf);
            }
        }
        if (diag) {
            int cc = t & 127;
            const uint32_t* Ph = (t < 128) ? &Ah[s][0] : &Bh[s][0];
            const uint32_t* Pl = (t < 128) ? &Al[s][0] : &Bl[s][0];
            float sa = 0.f;
            #pragma unroll
            for (int pp = 0; pp < 8; pp++) {
                __half2 hh = *(const __half2*)&Ph[off(cc, pp)];
                __half2 ll = *(const __half2*)&Pl[off(cc, pp)];
                sa += __low2float(hh) + __high2float(hh)
                    + __low2float(ll) + __high2float(ll);
            }
            colsum += sa;
        }
        if (zero0 && t < KT)
            cnt += mask_raw(mask, nbase + (long)i * KT + t, mode) ? 0.f : 1.f;
    }

    float* outp = d_Spart + ((long)(sp * NB + b) << 16);
    #pragma unroll
    for (int mi = 0; mi < 2; mi++) {
        int d = d0 + wn * 32 + mi * 16 + g;
        #pragma unroll
        for (int ni = 0; ni < 8; ni++) {
            int e = e0 + we * 64 + ni * 8 + 2 * tg;
            float2 v;
            v.x = acc[mi][ni][0]; v.y = acc[mi][ni][1];
            *(float2*)&outp[(long)d * DD + e] = v;
            v.x = acc[mi][ni][2]; v.y = acc[mi][ni][3];
            *(float2*)&outp[(long)(d + 8) * DD + e] = v;
        }
    }
    if (diag) {
        int cc = t & 127;
        if (t < 128) d_Upart[(sp * NB + b) * DD + d0 + cc] = colsum;
        else         d_Wpart[(sp * NB + b) * DD + e0 + cc] = colsum;
    }
    if (zero0) {
        if (t < KT) cntsh[t] = cnt;
        __syncthreads();
        if (t == 0) {
            float s = 0.f;
            #pragma unroll
            for (int k = 0; k < KT; k++) s += cntsh[k];
            d_Cpart[sp * NB + b] = s;
        }
    }
}

__global__ void s_reduce_kernel() {
    long i = (long)blockIdx.x * 256 + threadIdx.x;
    int b = (int)(i >> 16);
    int j = (int)(i & 65535);
    float s = 0.f;
    #pragma unroll
    for (int sp = 0; sp < NSPLIT; sp++)
        s += d_Spart[((long)(sp * NB + b) << 16) + j];
    d_S[((long)b << 16) + j] = s;
}

__global__ void uvw_reduce_kernel() {
    int b = blockIdx.x, d = threadIdx.x;
    float su = 0.f, sw = 0.f;
    #pragma unroll
    for (int sp = 0; sp < NSPLIT; sp++) {
        su += d_Upart[(sp * NB + b) * DD + d];
        sw += d_Wpart[(sp * NB + b) * DD + d];
    }
    d_u[b * DD + d] = su;
    d_w[b * DD + d] = sw;
    if (d == 0) {
        float c = 0.f;
        #pragma unroll
        for (int sp = 0; sp < NSPLIT; sp++) c += d_Cpart[sp * NB + b];
        d_cc[b] = c;
    }
}

__global__ void kv_kernel(const float* __restrict__ Wk,
                          const float* __restrict__ Wv,
                          const float* __restrict__ bv) {
    int b = blockIdx.x, d = threadIdx.x;
    __shared__ float su[DD], sw[DD];
    su[d] = d_u[b * DD + d];
    sw[d] = d_w[b * DD + d];
    __syncthreads();
    float s1 = 0.f, s2 = 0.f;
    for (int i = 0; i < DD; i++) {
        s1 = fmaf(Wk[(long)d * DD + i], su[i], s1);
        s2 = fmaf(Wv[(long)d * DD + i], sw[i], s2);
    }
    d_kv1[b * DD + d] = s1;
    d_kv2[b * DD + d] = s2 + d_cc[b] * bv[d];
}

// ---------------- small batched GEMM ----------------
template<bool TA, bool TB, bool EPI, bool SPL>
__global__ __launch_bounds__(128) void sgemm_k(
    const float* __restrict__ A, long sA,
    const float* __restrict__ B, long sB,
    float* __restrict__ C, __half* __restrict__ Ch, __half* __restrict__ Cl,
    const float* __restrict__ x1, int sx1,
    const float* __restrict__ y1, int sy1,
    const float* __restrict__ x2, int sx2,
    const float* __restrict__ y2, int sy2,
    float scale)
{
    __shared__ float As[16][36];
    __shared__ float Bs[16][68];
    int t = threadIdx.x;
    int b = blockIdx.z;
    int d0 = blockIdx.x * 32, e0 = blockIdx.y * 64;
    const float* Ab = A + (long)b * sA;
    const float* Bb = B + (long)b * sB;
    int td = t & 7, te = t >> 3;

    float acc[4][4];
    #pragma unroll
    for (int r = 0; r < 4; r++)
        #pragma unroll
        for (int c = 0; c < 4; c++) acc[r][c] = 0.f;

    for (int kt = 0; kt < DD; kt += 16) {
        if (TA) {
            int row = t >> 3, col = (t & 7) * 4;
            *(float4*)&As[row][col] = *(const float4*)&Ab[(long)(kt + row) * DD + d0 + col];
        } else {
            int row = t >> 2, col = (t & 3) * 4;
            float4 v = *(const float4*)&Ab[(long)(d0 + row) * DD + kt + col];
            As[col + 0][row] = v.x; As[col + 1][row] = v.y;
            As[col + 2][row] = v.z; As[col + 3][row] = v.w;
        }
        #pragma unroll
        for (int h = 0; h < 2; h++) {
            int idx = t * 4 + h * 512;
            if (TB) {
                int row = idx >> 4, col = idx & 15;
                float4 v = *(const float4*)&Bb[(long)(e0 + row) * DD + kt + col];
                Bs[col + 0][row] = v.x; Bs[col + 1][row] = v.y;
                Bs[col + 2][row] = v.z; Bs[col + 3][row] = v.w;
            } else {
                int row = idx >> 6, col = idx & 63;
                *(float4*)&Bs[row][col] = *(const float4*)&Bb[(long)(kt + row) * DD + e0 + col];
            }
        }
        __syncthreads();
        #pragma unroll
        for (int k = 0; k < 16; k++) {
            float4 a = *(const float4*)&As[k][td * 4];
            float4 bb = *(const float4*)&Bs[k][te * 4];
            float av[4] = {a.x, a.y, a.z, a.w};
            float bv2[4] = {bb.x, bb.y, bb.z, bb.w};
            #pragma unroll
            for (int r = 0; r < 4; r++)
                #pragma unroll
                for (int c = 0; c < 4; c++)
                    acc[r][c] = fmaf(av[r], bv2[c], acc[r][c]);
        }
        __syncthreads();
    }

    #pragma unroll
    for (int r = 0; r < 4; r++) {
        int d = d0 + td * 4 + r;
        #pragma unroll
        for (int c = 0; c < 4; c++) {
            int e = e0 + te * 4 + c;
            float v = acc[r][c];
            if (EPI)
                v = (v + x1[b * sx1 + d] * y1[b * sy1 + e]
                       + x2[b * sx2 + d] * y2[b * sy2 + e]) * scale;
            long offo = ((long)b << 16) + (long)d * DD + e;
            if (SPL) {
                __half h = __float2half_rn(v);
                Ch[offo] = h;
                Cl[offo] = __float2half_rn(v - __half2float(h));
            } else {
                C[offo] = v;
            }
        }
    }
}

// ---------------- softmax / rvec ----------------
__global__ void softmax_kernel() {
    int b = blockIdx.x, ec = blockIdx.y;
    int tx = threadIdx.x, ty = threadIdx.y;
    float* Pb = d_P + ((long)b << 16);
    int e = ec * 64 + tx;
    __shared__ float red[4][64];

    float mx = -3.4e38f;
    for (int d = ty; d < DD; d += 4) mx = fmaxf(mx, Pb[(long)d * DD + e]);
    red[ty][tx] = mx;
    __syncthreads();
    mx = fmaxf(fmaxf(red[0][tx], red[1][tx]), fmaxf(red[2][tx], red[3][tx]));
    __syncthreads();
    float s = 0.f;
    for (int d = ty; d < DD; d += 4) {
        float ev = expf(Pb[(long)d * DD + e] - mx);
        Pb[(long)d * DD + e] = ev;
        s += ev;
    }
    red[ty][tx] = s;
    __syncthreads();
    float inv = 1.0f / (red[0][tx] + red[1][tx] + red[2][tx] + red[3][tx]);
    for (int d = ty; d < DD; d += 4) Pb[(long)d * DD + e] *= inv;
}

__global__ void rvec_kernel(const float* __restrict__ bq) {
    int b = blockIdx.x, e = threadIdx.x;
    const float* Pb = d_P + ((long)b << 16);
    float s = 0.f;
    for (int d = 0; d < DD; d++) s = fmaf(bq[d], Pb[(long)d * DD + e], s);
    d_r[b * DD + e] = s;
}

// ---------------- stage 3: out = q @ M + r  (fp16x3 mma) -------------------
// CTA 128n x 128e, K=256 in chunks of 32, double buffered.
// A = query (split in-kernel, k-major, no transpose); B = Mt pre-split halves.
// smem per array: 128 rows x 5 16B-units (4 used + pad), 16B xor swizzle.
#define S3_SMEM (2 * 2560 * 16)

__device__ __forceinline__ int offA32(int r, int kp) {
    return (r * 5 + ((kp >> 2) ^ (r & 3))) * 4 + (kp & 3);
}

__global__ __launch_bounds__(256, 1) void stage3_kernel(
    const float* __restrict__ query, float* __restrict__ out)
{
    extern __shared__ uint4 sm[];
    __shared__ float rsh[DD];
    int t = threadIdx.x, lane = t & 31, wid = t >> 5;
    int b = blockIdx.z;
    long n0 = (long)blockIdx.x * 128;
    int e0 = blockIdx.y * 128;
    const float* qb = query + ((long)b * NN + n0) * DD;
    const __half* Bhp = d_Mth + ((long)b << 16) + (long)e0 * DD;
    const __half* Blp = d_Mtl + ((long)b << 16) + (long)e0 * DD;
    if (t < DD) rsh[t] = d_r[b * DD + t];

    int wn = wid & 3, we = wid >> 2, g = lane >> 2, tg = lane & 3;

    auto issueB = [&](int c, int s) {
        uint4* BH = sm + s * 2560 + 1280;
        uint4* BL = BH + 640;
        #pragma unroll
        for (int a = 0; a < 2; a++) {
            int idx = t + a * 256, e = idx >> 2, u = idx & 3;
            int i16 = e * 5 + (u ^ (e & 3));
            cpa16(&BH[i16], Bhp + (long)e * DD + c * 32 + u * 8);
            cpa16(&BL[i16], Blp + (long)e * DD + c * 32 + u * 8);
        }
        CPA_COMMIT();
    };
    auto loadA = [&](int c, int s) {
        uint4* AH = sm + s * 2560;
        uint4* AL = AH + 640;
        #pragma unroll
        for (int a = 0; a < 2; a++) {
            int idx = t + a * 256, row = idx >> 2, u = idx & 3;
            const float* src = qb + (long)row * DD + c * 32 + u * 8;
            float4 f0 = *(const float4*)src;
            float4 f1 = *(const float4*)(src + 4);
            uint32_t h0, l0, h1, l1, h2, l2, h3, l3;
            split2(f0.x, f0.y, h0, l0); split2(f0.z, f0.w, h1, l1);
            split2(f1.x, f1.y, h2, l2); split2(f1.z, f1.w, h3, l3);
            int i16 = row * 5 + (u ^ (row & 3));
            AH[i16] = make_uint4(h0, h1, h2, h3);
            AL[i16] = make_uint4(l0, l1, l2, l3);
        }
    };

    float acc[2][8][4];
    #pragma unroll
    for (int mi = 0; mi < 2; mi++)
        #pragma unroll
        for (int ni = 0; ni < 8; ni++)
            #pragma unroll
            for (int j = 0; j < 4; j++) acc[mi][ni][j] = 0.f;

    issueB(0, 0);

    for (int c = 0; c < 8; c++) {
        int s = c & 1;
        loadA(c, s);
        if (c < 7) { issueB(c + 1, 1 - s); CPA_WAIT(1); }
        else       { CPA_WAIT(0); }
        __syncthreads();

        const uint32_t* AH = (const uint32_t*)(sm + s * 2560);
        const uint32_t* AL = AH + 2560;
        const uint32_t* BH = AH + 5120;
        const uint32_t* BL = AH + 7680;
        #pragma unroll
        for (int j = 0; j < 2; j++) {
            int kp0 = j * 8 + tg, kp1 = kp0 + 4;
            uint32_t ah[2][4], al[2][4];
            #pragma unroll
            for (int mi = 0; mi < 2; mi++) {
                int r = wn * 32 + mi * 16 + g;
                ah[mi][0] = AH[offA32(r, kp0)];     ah[mi][1] = AH[offA32(r + 8, kp0)];
                ah[mi][2] = AH[offA32(r, kp1)];     ah[mi][3] = AH[offA32(r + 8, kp1)];
                al[mi][0] = AL[offA32(r, kp0)];     al[mi][1] = AL[offA32(r + 8, kp0)];
                al[mi][2] = AL[offA32(r, kp1)];     al[mi][3] = AL[offA32(r + 8, kp1)];
            }
            #pragma unroll
            for (int ni = 0; ni < 8; ni++) {
                int e = we * 64 + ni * 8 + g;
                uint32_t bhf[2] = {BH[offA32(e, kp0)], BH[offA32(e, kp1)]};
                uint32_t blf[2] = {BL[offA32(e, kp0)], BL[offA32(e, kp1)]};
                #pragma unroll
                for (int mi = 0; mi < 2; mi++) {
                    mma16816(acc[mi][ni], ah[mi], bhf);
                    mma16816(acc[mi][ni], ah[mi], blf);
                    mma16816(acc[mi][ni], al[mi], bhf);
                }
            }
        }
        __syncthreads();
    }

    #pragma unroll
    for (int mi = 0; mi < 2; mi++) {
        long nr = n0 + wn * 32 + mi * 16;
        #pragma unroll
        for (int ni = 0; ni < 8; ni++) {
            int eg = e0 + we * 64 + ni * 8 + tg * 2;
            float2 v0, v1;
            v0.x = acc[mi][ni][0] + rsh[eg];
            v0.y = acc[mi][ni][1] + rsh[eg + 1];
            v1.x = acc[mi][ni][2] + rsh[eg];
            v1.y = acc[mi][ni][3] + rsh[eg + 1];
            *(float2*)(out + ((long)b * NN + nr + g) * DD + eg) = v0;
            *(float2*)(out + ((long)b * NN + nr + g + 8) * DD + eg) = v1;
        }
    }
}

// ---------------------------------------------------------------------------
extern "C" void kernel_launch(void* const* d_in, const int* in_sizes, int n_in,
                              void* d_out, int out_size)
{
    const float* query = (const float*)d_in[0];
    const float* key   = (const float*)d_in[1];
    const float* value = (const float*)d_in[2];
    const void*  mask  = d_in[3];
    int wo = (n_in >= 11 && in_sizes[4] == 1) ? 5 : 4;
    const float* Wq = (const float*)d_in[wo + 0];
    const float* bq = (const float*)d_in[wo + 1];
    const float* Wk = (const float*)d_in[wo + 2];
    const float* bk = (const float*)d_in[wo + 3];
    const float* Wv = (const float*)d_in[wo + 4];
    const float* bv = (const float*)d_in[wo + 5];
    float* out = (float*)d_out;

    float *pS, *pT1, *pP, *pkv1, *pkv2;
    __half *pMth, *pMtl;
    cudaGetSymbolAddress((void**)&pS, d_S);
    cudaGetSymbolAddress((void**)&pT1, d_T1);
    cudaGetSymbolAddress((void**)&pP, d_P);
    cudaGetSymbolAddress((void**)&pMth, d_Mth);
    cudaGetSymbolAddress((void**)&pMtl, d_Mtl);
    cudaGetSymbolAddress((void**)&pkv1, d_kv1);
    cudaGetSymbolAddress((void**)&pkv2, d_kv2);

    cudaFuncSetAttribute(stage3_kernel,
                         cudaFuncAttributeMaxDynamicSharedMemorySize, S3_SMEM);

    const float inv_sqrt8 = 0.35355339059327373f;

    detect_mask_kernel<<<1, 256>>>((const unsigned int*)mask);
    stage1_kernel<<<dim3(2, 2, NB * NSPLIT), 256>>>(key, value, mask);
    s_reduce_kernel<<<NB * DD * DD / 256, 256>>>();
    uvw_reduce_kernel<<<NB, DD>>>();
    kv_kernel<<<NB, DD>>>(Wk, Wv, bv);
    // T1 = Wk @ S
    sgemm_k<false, false, false, false><<<dim3(8, 4, NB), 128>>>(
        Wk, 0, pS, (long)DD * DD, pT1, nullptr, nullptr,
        nullptr, 0, nullptr, 0, nullptr, 0, nullptr, 0, 1.0f);
    // P = (T1 @ Wv^T + kv1*bv^T + bk*kv2^T) / sqrt(8)
    sgemm_k<false, true, true, false><<<dim3(8, 4, NB), 128>>>(
        pT1, (long)DD * DD, Wv, 0, pP, nullptr, nullptr,
        pkv1, DD, bv, 0, bk, 0, pkv2, DD, inv_sqrt8);
    softmax_kernel<<<dim3(NB, 4), dim3(64, 4)>>>();
    rvec_kernel<<<NB, DD>>>(bq);
    // Mt[e][d] = (aw^T @ Wq), fp16 hi/lo split epilogue
    sgemm_k<true, false, false, true><<<dim3(8, 4, NB), 128>>>(
        pP, (long)DD * DD, Wq, 0, nullptr, pMth, pMtl,
        nullptr, 0, nullptr, 0, nullptr, 0, nullptr, 0, 1.0f);
    stage3_kernel<<<dim3(64, 2, NB), 256, S3_SMEM>>>(query, out);
}